// round 8
// baseline (speedup 1.0000x reference)
#include <cuda_runtime.h>
#include <cuda_bf16.h>
#include <math.h>
#include <stdint.h>

// Problem constants
#define B_  4
#define T_  2048
#define D_  1024
#define H_  16
#define DH_ 64

typedef unsigned short u16;

// ---------------------------------------------------------------------------
// Scratch (allocation-free rule: __device__ globals)
// ---------------------------------------------------------------------------
__device__ u16 g_xhi[(size_t)B_ * T_ * D_];
__device__ u16 g_xlo[(size_t)B_ * T_ * D_];
__device__ u16 g_wahi[(size_t)3 * D_ * D_];
__device__ u16 g_walo[(size_t)3 * D_ * D_];
__device__ u16 g_wphi[(size_t)D_ * D_];
__device__ u16 g_wplo[(size_t)D_ * D_];
__device__ u16 g_qkvh[(size_t)B_ * T_ * 3 * D_];
__device__ u16 g_qkvl[(size_t)B_ * T_ * 3 * D_];
__device__ u16 g_yhi[(size_t)B_ * T_ * D_];
__device__ u16 g_ylo[(size_t)B_ * T_ * D_];

// ---------------------------------------------------------------------------
// Helpers
// ---------------------------------------------------------------------------
__device__ __forceinline__ uint32_t smem_u32(const void* p) {
    uint32_t a;
    asm("{ .reg .u64 t; cvta.to.shared.u64 t, %1; cvt.u32.u64 %0, t; }"
        : "=r"(a) : "l"(p));
    return a;
}

__device__ __forceinline__ void mma_bf16_16816(
    float c[4], uint32_t a0, uint32_t a1, uint32_t a2, uint32_t a3,
    uint32_t b0, uint32_t b1)
{
    asm volatile(
        "mma.sync.aligned.m16n8k16.row.col.f32.bf16.bf16.f32 "
        "{%0,%1,%2,%3}, {%4,%5,%6,%7}, {%8,%9}, {%0,%1,%2,%3};"
        : "+f"(c[0]), "+f"(c[1]), "+f"(c[2]), "+f"(c[3])
        : "r"(a0), "r"(a1), "r"(a2), "r"(a3), "r"(b0), "r"(b1));
}

#define LDMX4(r, addr) \
    asm volatile("ldmatrix.sync.aligned.m8n8.x4.shared.b16 {%0,%1,%2,%3}, [%4];" \
        : "=r"((r)[0]), "=r"((r)[1]), "=r"((r)[2]), "=r"((r)[3]) : "r"(addr))
#define LDMX4T(r, addr) \
    asm volatile("ldmatrix.sync.aligned.m8n8.x4.trans.shared.b16 {%0,%1,%2,%3}, [%4];" \
        : "=r"((r)[0]), "=r"((r)[1]), "=r"((r)[2]), "=r"((r)[3]) : "r"(addr))

__device__ __forceinline__ uint32_t split_pack(float f0, float f1, uint32_t& lop) {
    __nv_bfloat16 h0 = __float2bfloat16(f0);
    __nv_bfloat16 h1 = __float2bfloat16(f1);
    __nv_bfloat16 l0 = __float2bfloat16(f0 - __bfloat162float(h0));
    __nv_bfloat16 l1 = __float2bfloat16(f1 - __bfloat162float(h1));
    lop = (uint32_t)__bfloat16_as_ushort(l0) | ((uint32_t)__bfloat16_as_ushort(l1) << 16);
    return (uint32_t)__bfloat16_as_ushort(h0) | ((uint32_t)__bfloat16_as_ushort(h1) << 16);
}

#define CP_ASYNC16(dst, src) \
    asm volatile("cp.async.cg.shared.global [%0], [%1], 16;" :: "r"(dst), "l"(src))
#define CP_COMMIT() asm volatile("cp.async.commit_group;")
#define CP_WAIT1()  asm volatile("cp.async.wait_group 1;")
#define CP_WAIT0()  asm volatile("cp.async.wait_group 0;")

// ---------------------------------------------------------------------------
// Split fp32 -> bf16 (hi, lo) pair
// ---------------------------------------------------------------------------
__global__ __launch_bounds__(256) void split_bf16_kernel(
    const float* __restrict__ in, u16* __restrict__ hi,
    u16* __restrict__ lo, int n4)
{
    int i = blockIdx.x * 256 + threadIdx.x;
    if (i >= n4) return;
    float4 v = ((const float4*)in)[i];
    uint32_t lp0, lp1;
    uint32_t hp0 = split_pack(v.x, v.y, lp0);
    uint32_t hp1 = split_pack(v.z, v.w, lp1);
    ((uint2*)hi)[i] = make_uint2(hp0, hp1);
    ((uint2*)lo)[i] = make_uint2(lp0, lp1);
}

// ---------------------------------------------------------------------------
// HMMA GEMM, cp.async double-buffered, ldmatrix fragment loads (unchanged R7).
// ---------------------------------------------------------------------------
#define KPADB 80
#define ARR_SZ 10240
#define STAGE_SZ 40960
#define GEMM_SMEM (2 * STAGE_SZ)

template<bool SPLIT_OUT>
__global__ __launch_bounds__(256) void gemm_mma_db(
    const u16* __restrict__ Ahi, const u16* __restrict__ Alo,
    const u16* __restrict__ Bhi, const u16* __restrict__ Blo,
    float* __restrict__ Cf, u16* __restrict__ Chi, u16* __restrict__ Clo,
    int M, int N, int K)
{
    extern __shared__ char smc[];
    const uint32_t sb = smem_u32(smc);

    const int tid = threadIdx.x;
    const int wid = tid >> 5;
    const int lane = tid & 31;
    const int g = lane >> 2;
    const int t = lane & 3;
    const int warp_m = (wid >> 2) * 64;
    const int warp_n = (wid & 3) * 32;
    const int bm = blockIdx.y * 128;
    const int bn = blockIdx.x * 128;

    const int a_r = (lane & 7) + ((lane >> 3) & 1) * 8;
    const int a_k = (lane >> 4) * 8;
    const int b_r = (lane & 7) + (lane >> 4) * 8;
    const int b_k = ((lane >> 3) & 1) * 8;

    float acc[4][4][4];
    #pragma unroll
    for (int i = 0; i < 4; i++)
        #pragma unroll
        for (int j = 0; j < 4; j++)
            #pragma unroll
            for (int r = 0; r < 4; r++) acc[i][j][r] = 0.0f;

    auto prefetch = [&](int k0, int s) {
        #pragma unroll
        for (int c = 0; c < 2; c++) {
            int ch = tid + c * 256;
            int row = ch >> 2;
            int cq = ch & 3;
            uint32_t so = sb + s * STAGE_SZ + row * KPADB + cq * 16;
            size_t ga = (size_t)(bm + row) * K + k0 + cq * 8;
            size_t gb = (size_t)(bn + row) * K + k0 + cq * 8;
            CP_ASYNC16(so + 0 * ARR_SZ, Ahi + ga);
            CP_ASYNC16(so + 1 * ARR_SZ, Alo + ga);
            CP_ASYNC16(so + 2 * ARR_SZ, Bhi + gb);
            CP_ASYNC16(so + 3 * ARR_SZ, Blo + gb);
        }
        CP_COMMIT();
    };

    const int nt = K / 32;
    prefetch(0, 0);

    for (int ti = 0; ti < nt; ti++) {
        if (ti + 1 < nt) { prefetch((ti + 1) * 32, (ti + 1) & 1); CP_WAIT1(); }
        else             { CP_WAIT0(); }
        __syncthreads();

        const uint32_t st = sb + (ti & 1) * STAGE_SZ;
        const uint32_t sAh = st + 0 * ARR_SZ;
        const uint32_t sAl = st + 1 * ARR_SZ;
        const uint32_t sBh = st + 2 * ARR_SZ;
        const uint32_t sBl = st + 3 * ARR_SZ;

        #pragma unroll
        for (int ks = 0; ks < 2; ks++) {
            const int kb = ks * 16;

            uint32_t ah[4][4], al[4][4], bh[2][4], bl[2][4];
            #pragma unroll
            for (int mf = 0; mf < 4; mf++) {
                uint32_t off = (uint32_t)(warp_m + mf * 16 + a_r) * KPADB
                             + (uint32_t)(kb + a_k) * 2;
                LDMX4(ah[mf], sAh + off);
                LDMX4(al[mf], sAl + off);
            }
            #pragma unroll
            for (int nf2 = 0; nf2 < 2; nf2++) {
                uint32_t off = (uint32_t)(warp_n + nf2 * 16 + b_r) * KPADB
                             + (uint32_t)(kb + b_k) * 2;
                LDMX4(bh[nf2], sBh + off);
                LDMX4(bl[nf2], sBl + off);
            }

            #pragma unroll
            for (int mf = 0; mf < 4; mf++)
                #pragma unroll
                for (int nf = 0; nf < 4; nf++)
                    mma_bf16_16816(acc[mf][nf],
                                   ah[mf][0], ah[mf][1], ah[mf][2], ah[mf][3],
                                   bh[nf >> 1][(nf & 1) * 2],
                                   bh[nf >> 1][(nf & 1) * 2 + 1]);
            #pragma unroll
            for (int mf = 0; mf < 4; mf++)
                #pragma unroll
                for (int nf = 0; nf < 4; nf++)
                    mma_bf16_16816(acc[mf][nf],
                                   ah[mf][0], ah[mf][1], ah[mf][2], ah[mf][3],
                                   bl[nf >> 1][(nf & 1) * 2],
                                   bl[nf >> 1][(nf & 1) * 2 + 1]);
            #pragma unroll
            for (int mf = 0; mf < 4; mf++)
                #pragma unroll
                for (int nf = 0; nf < 4; nf++)
                    mma_bf16_16816(acc[mf][nf],
                                   al[mf][0], al[mf][1], al[mf][2], al[mf][3],
                                   bh[nf >> 1][(nf & 1) * 2],
                                   bh[nf >> 1][(nf & 1) * 2 + 1]);
        }
        __syncthreads();
    }

    #pragma unroll
    for (int mf = 0; mf < 4; mf++) {
        #pragma unroll
        for (int nf = 0; nf < 4; nf++) {
            int row = bm + warp_m + mf * 16 + g;
            int col = bn + warp_n + nf * 8 + t * 2;
            if (SPLIT_OUT) {
                uint32_t lp;
                uint32_t hp = split_pack(acc[mf][nf][0], acc[mf][nf][1], lp);
                *(uint32_t*)&Chi[(size_t)row * N + col] = hp;
                *(uint32_t*)&Clo[(size_t)row * N + col] = lp;
                hp = split_pack(acc[mf][nf][2], acc[mf][nf][3], lp);
                *(uint32_t*)&Chi[(size_t)(row + 8) * N + col] = hp;
                *(uint32_t*)&Clo[(size_t)(row + 8) * N + col] = lp;
            } else {
                *(float2*)(Cf + (size_t)row * N + col) =
                    make_float2(acc[mf][nf][0], acc[mf][nf][1]);
                *(float2*)(Cf + (size_t)(row + 8) * N + col) =
                    make_float2(acc[mf][nf][2], acc[mf][nf][3]);
            }
        }
    }
}

// ---------------------------------------------------------------------------
// Flash attention, 128-row q-tile, 256 threads (8 warps), K/V double-buffered.
// Warp w owns q rows w*16..w*16+15 of the 128-row tile. kv tiles of 64 rows.
// ---------------------------------------------------------------------------
#define AROWB 144                       // bytes per padded 64-col row
#define Q_ARR (128 * AROWB)             // 18432
#define A_QH 0
#define A_QL Q_ARR
#define KV_BASE (2 * Q_ARR)             // 36864
#define KV_ARR (64 * AROWB)             // 9216
#define KV_STG (4 * KV_ARR)             // 36864
#define ATTN_SMEM (KV_BASE + 2 * KV_STG)  // 110592

__global__ __launch_bounds__(256) void attn_mma_kernel(
    const u16* __restrict__ qh, const u16* __restrict__ ql,
    u16* __restrict__ yhi, u16* __restrict__ ylo)
{
    extern __shared__ char sm_[];
    const uint32_t sbase = smem_u32(sm_);
    const int qt = blockIdx.x;          // 0..15 (128-row tiles)
    const int h  = blockIdx.y;
    const int b  = blockIdx.z;
    const int tid = threadIdx.x;
    const int wid = tid >> 5;           // 0..7
    const int lane = tid & 31;
    const int g = lane >> 2;
    const int t = lane & 3;
    const int wm = wid * 16;

    const int a_r = (lane & 7) + ((lane >> 3) & 1) * 8;
    const int a_k = (lane >> 4) * 8;
    const int b_r = (lane & 7) + (lane >> 4) * 8;
    const int b_k = ((lane >> 3) & 1) * 8;

    // Load Q tile (128x64, hi/lo) via cp.async: 1024 chunks/array, 4/thread.
    #pragma unroll
    for (int i = 0; i < 4; i++) {
        int slot = tid + i * 256;
        int r = slot >> 3;
        int c8 = (slot & 7) * 8;
        size_t gq = (size_t)(b * T_ + qt * 128 + r) * (3 * D_) + h * 64 + c8;
        uint32_t so = sbase + r * AROWB + c8 * 2;
        CP_ASYNC16(so + A_QH, qh + gq);
        CP_ASYNC16(so + A_QL, ql + gq);
    }
    CP_COMMIT();

    auto prefetch_kv = [&](int kt, int s) {
        uint32_t stb = sbase + KV_BASE + s * KV_STG;
        #pragma unroll
        for (int i = 0; i < 2; i++) {
            int slot = tid + i * 256;   // 0..511
            int r = slot >> 3;          // 0..63
            int c8 = (slot & 7) * 8;
            size_t gk = (size_t)(b * T_ + kt * 64 + r) * (3 * D_) + D_ + h * 64 + c8;
            uint32_t so = stb + r * AROWB + c8 * 2;
            CP_ASYNC16(so + 0 * KV_ARR, qh + gk);        // KH
            CP_ASYNC16(so + 1 * KV_ARR, ql + gk);        // KL
            CP_ASYNC16(so + 2 * KV_ARR, qh + gk + D_);   // VH
            CP_ASYNC16(so + 3 * KV_ARR, ql + gk + D_);   // VL
        }
        CP_COMMIT();
    };

    prefetch_kv(0, 0);

    float m0 = -1e30f, m1 = -1e30f, l0 = 0.0f, l1 = 0.0f;
    float o[8][4];
    #pragma unroll
    for (int nf = 0; nf < 8; nf++)
        #pragma unroll
        for (int r = 0; r < 4; r++) o[nf][r] = 0.0f;

    const int ktmax = 2 * qt + 1;
    for (int kt = 0; kt <= ktmax; kt++) {
        CP_WAIT0();
        __syncthreads();
        if (kt < ktmax) prefetch_kv(kt + 1, (kt + 1) & 1);

        const uint32_t stb = sbase + KV_BASE + (kt & 1) * KV_STG;
        const uint32_t sKH = stb + 0 * KV_ARR;
        const uint32_t sKL = stb + 1 * KV_ARR;
        const uint32_t sVH = stb + 2 * KV_ARR;
        const uint32_t sVL = stb + 3 * KV_ARR;

        // ---- S = Q @ K^T (split-3, ldmatrix) ----
        float s[8][4];
        #pragma unroll
        for (int nf = 0; nf < 8; nf++)
            #pragma unroll
            for (int r = 0; r < 4; r++) s[nf][r] = 0.0f;

        #pragma unroll
        for (int ks = 0; ks < 4; ks++) {
            const int kb = ks * 16;
            uint32_t ah[4], al[4], kh[4][4], kl[4][4];
            {
                uint32_t off = (uint32_t)(wm + a_r) * AROWB + (uint32_t)(kb + a_k) * 2;
                LDMX4(ah, sbase + A_QH + off);
                LDMX4(al, sbase + A_QL + off);
            }
            #pragma unroll
            for (int nf2 = 0; nf2 < 4; nf2++) {
                uint32_t off = (uint32_t)(nf2 * 16 + b_r) * AROWB
                             + (uint32_t)(kb + b_k) * 2;
                LDMX4(kh[nf2], sKH + off);
                LDMX4(kl[nf2], sKL + off);
            }
            #pragma unroll
            for (int nf = 0; nf < 8; nf++)
                mma_bf16_16816(s[nf], ah[0], ah[1], ah[2], ah[3],
                               kh[nf >> 1][(nf & 1) * 2], kh[nf >> 1][(nf & 1) * 2 + 1]);
            #pragma unroll
            for (int nf = 0; nf < 8; nf++)
                mma_bf16_16816(s[nf], ah[0], ah[1], ah[2], ah[3],
                               kl[nf >> 1][(nf & 1) * 2], kl[nf >> 1][(nf & 1) * 2 + 1]);
            #pragma unroll
            for (int nf = 0; nf < 8; nf++)
                mma_bf16_16816(s[nf], al[0], al[1], al[2], al[3],
                               kh[nf >> 1][(nf & 1) * 2], kh[nf >> 1][(nf & 1) * 2 + 1]);
        }

        #pragma unroll
        for (int nf = 0; nf < 8; nf++)
            #pragma unroll
            for (int r = 0; r < 4; r++) s[nf][r] *= 0.125f;

        // causal mask (only the two diagonal kv-tiles of this q-tile)
        if (kt * 64 + 63 > qt * 128 + wm) {
            int r0 = qt * 128 + wm + g;
            int r1 = r0 + 8;
            #pragma unroll
            for (int nf = 0; nf < 8; nf++) {
                int col = kt * 64 + nf * 8 + t * 2;
                if (col > r0)     s[nf][0] = -1e30f;
                if (col + 1 > r0) s[nf][1] = -1e30f;
                if (col > r1)     s[nf][2] = -1e30f;
                if (col + 1 > r1) s[nf][3] = -1e30f;
            }
        }

        // ---- online softmax ----
        float rm0 = -1e30f, rm1 = -1e30f;
        #pragma unroll
        for (int nf = 0; nf < 8; nf++) {
            rm0 = fmaxf(rm0, fmaxf(s[nf][0], s[nf][1]));
            rm1 = fmaxf(rm1, fmaxf(s[nf][2], s[nf][3]));
        }
        rm0 = fmaxf(rm0, __shfl_xor_sync(0xffffffffu, rm0, 1));
        rm0 = fmaxf(rm0, __shfl_xor_sync(0xffffffffu, rm0, 2));
        rm1 = fmaxf(rm1, __shfl_xor_sync(0xffffffffu, rm1, 1));
        rm1 = fmaxf(rm1, __shfl_xor_sync(0xffffffffu, rm1, 2));

        float mn0 = fmaxf(m0, rm0), mn1 = fmaxf(m1, rm1);
        float a0 = __expf(m0 - mn0), a1 = __expf(m1 - mn1);

        float rs0 = 0.0f, rs1 = 0.0f;
        uint32_t phg[8], phg8[8], plg[8], plg8[8];
        #pragma unroll
        for (int nf = 0; nf < 8; nf++) {
            float p0 = __expf(s[nf][0] - mn0);
            float p1 = __expf(s[nf][1] - mn0);
            float p2 = __expf(s[nf][2] - mn1);
            float p3 = __expf(s[nf][3] - mn1);
            rs0 += p0 + p1;
            rs1 += p2 + p3;
            phg[nf]  = split_pack(p0, p1, plg[nf]);
            phg8[nf] = split_pack(p2, p3, plg8[nf]);
        }
        rs0 += __shfl_xor_sync(0xffffffffu, rs0, 1);
        rs0 += __shfl_xor_sync(0xffffffffu, rs0, 2);
        rs1 += __shfl_xor_sync(0xffffffffu, rs1, 1);
        rs1 += __shfl_xor_sync(0xffffffffu, rs1, 2);

        l0 = l0 * a0 + rs0;
        l1 = l1 * a1 + rs1;
        m0 = mn0;
        m1 = mn1;
        #pragma unroll
        for (int nf = 0; nf < 8; nf++) {
            o[nf][0] *= a0; o[nf][1] *= a0;
            o[nf][2] *= a1; o[nf][3] *= a1;
        }

        // ---- O += P @ V (split-3, ldmatrix.trans for V^T) ----
        #pragma unroll
        for (int j = 0; j < 4; j++) {
            const int k0 = j * 16;
            uint32_t vh[4][4], vl[4][4];
            #pragma unroll
            for (int nf2 = 0; nf2 < 4; nf2++) {
                uint32_t off = (uint32_t)(k0 + a_r) * AROWB
                             + (uint32_t)(nf2 * 16 + a_k) * 2;
                LDMX4T(vh[nf2], sVH + off);
                LDMX4T(vl[nf2], sVL + off);
            }
            uint32_t pa0 = phg[2 * j],     pa1 = phg8[2 * j];
            uint32_t pa2 = phg[2 * j + 1], pa3 = phg8[2 * j + 1];
            uint32_t qa0 = plg[2 * j],     qa1 = plg8[2 * j];
            uint32_t qa2 = plg[2 * j + 1], qa3 = plg8[2 * j + 1];
            #pragma unroll
            for (int nf = 0; nf < 8; nf++)
                mma_bf16_16816(o[nf], pa0, pa1, pa2, pa3,
                               vh[nf >> 1][(nf & 1) * 2], vh[nf >> 1][(nf & 1) * 2 + 1]);
            #pragma unroll
            for (int nf = 0; nf < 8; nf++)
                mma_bf16_16816(o[nf], pa0, pa1, pa2, pa3,
                               vl[nf >> 1][(nf & 1) * 2], vl[nf >> 1][(nf & 1) * 2 + 1]);
            #pragma unroll
            for (int nf = 0; nf < 8; nf++)
                mma_bf16_16816(o[nf], qa0, qa1, qa2, qa3,
                               vh[nf >> 1][(nf & 1) * 2], vh[nf >> 1][(nf & 1) * 2 + 1]);
        }
    }

    // ---- epilogue ----
    float inv0 = 1.0f / l0, inv1 = 1.0f / l1;
    #pragma unroll
    for (int nf = 0; nf < 8; nf++) {
        int col = h * 64 + nf * 8 + t * 2;
        size_t r0 = (size_t)(b * T_ + qt * 128 + wm + g) * D_ + col;
        size_t r1 = r0 + 8 * D_;
        uint32_t lp;
        uint32_t hp = split_pack(o[nf][0] * inv0, o[nf][1] * inv0, lp);
        *(uint32_t*)&yhi[r0] = hp;
        *(uint32_t*)&ylo[r0] = lp;
        hp = split_pack(o[nf][2] * inv1, o[nf][3] * inv1, lp);
        *(uint32_t*)&yhi[r1] = hp;
        *(uint32_t*)&ylo[r1] = lp;
    }
}

// ---------------------------------------------------------------------------
// Launch
// ---------------------------------------------------------------------------
extern "C" void kernel_launch(void* const* d_in, const int* in_sizes, int n_in,
                              void* d_out, int out_size)
{
    const float* x      = (const float*)d_in[0];
    const float* w_attn = (const float*)d_in[1];
    const float* w_proj = (const float*)d_in[2];
    float* out = (float*)d_out;

    u16 *xhi, *xlo, *wahi, *walo, *wphi, *wplo, *qkvh, *qkvl, *yhi, *ylo;
    cudaGetSymbolAddress((void**)&xhi,  g_xhi);
    cudaGetSymbolAddress((void**)&xlo,  g_xlo);
    cudaGetSymbolAddress((void**)&wahi, g_wahi);
    cudaGetSymbolAddress((void**)&walo, g_walo);
    cudaGetSymbolAddress((void**)&wphi, g_wphi);
    cudaGetSymbolAddress((void**)&wplo, g_wplo);
    cudaGetSymbolAddress((void**)&qkvh, g_qkvh);
    cudaGetSymbolAddress((void**)&qkvl, g_qkvl);
    cudaGetSymbolAddress((void**)&yhi,  g_yhi);
    cudaGetSymbolAddress((void**)&ylo,  g_ylo);

    cudaFuncSetAttribute(gemm_mma_db<true>,
                         cudaFuncAttributeMaxDynamicSharedMemorySize, GEMM_SMEM);
    cudaFuncSetAttribute(gemm_mma_db<false>,
                         cudaFuncAttributeMaxDynamicSharedMemorySize, GEMM_SMEM);
    cudaFuncSetAttribute(attn_mma_kernel,
                         cudaFuncAttributeMaxDynamicSharedMemorySize, ATTN_SMEM);

    const int M = B_ * T_;   // 8192

    split_bf16_kernel<<<(B_ * T_ * D_ / 4 + 255) / 256, 256>>>(x, xhi, xlo, B_ * T_ * D_ / 4);
    split_bf16_kernel<<<(3 * D_ * D_ / 4 + 255) / 256, 256>>>(w_attn, wahi, walo, 3 * D_ * D_ / 4);
    split_bf16_kernel<<<(D_ * D_ / 4 + 255) / 256, 256>>>(w_proj, wphi, wplo, D_ * D_ / 4);

    gemm_mma_db<true><<<dim3((3 * D_) / 128, M / 128), 256, GEMM_SMEM>>>(
        xhi, xlo, wahi, walo, nullptr, qkvh, qkvl, M, 3 * D_, D_);

    attn_mma_kernel<<<dim3(T_ / 128, H_, B_), 256, ATTN_SMEM>>>(qkvh, qkvl, yhi, ylo);

    gemm_mma_db<false><<<dim3(D_ / 128, M / 128), 256, GEMM_SMEM>>>(
        yhi, ylo, wphi, wplo, out, nullptr, nullptr, M, D_, D_);
}